// round 3
// baseline (speedup 1.0000x reference)
#include <cuda_runtime.h>
#include <math.h>

// Problem sizes
#define QN 512
#define LN 4096

// ---------------- scratch (device globals; no allocation allowed) ----------------
__device__ float g_p [LN * 256];   // relu(protein @ Wc.T + bc)
__device__ float g_k [LN * 64];    // relu(p @ W1.T + b1)
__device__ float g_pa[LN * 64];    // k @ Wpa.T + bpa
__device__ float g_Sp[LN * 64];    // sum_q relu(ra+pa)
__device__ float g_r [QN * 64];    // relu(reactions @ W2.T + b2)
__device__ float g_ra[QN * 64];    // r @ Wra.T + bra
__device__ float g_Sr[QN * 64];    // sum_l relu(ra+pa)
__device__ float g_prot[64];       // max_l (k * (1+p_gate))

// ---------------- init: zero the atomic accumulators ----------------
__global__ void zero_init_kernel() {
    int i = blockIdx.x * blockDim.x + threadIdx.x;
    int stride = gridDim.x * blockDim.x;
    for (int x = i; x < LN * 64; x += stride) g_Sp[x] = 0.f;
    for (int x = i; x < QN * 64; x += stride) g_Sr[x] = 0.f;
    if (i < 64) g_prot[i] = 0.f;
}

// ---------------- tiled SGEMM: C = relu(A[M,K] @ B[N,K].T + bias) ----------------
template <int BM, int BN, int BK, int TM, int TN>
__global__ void __launch_bounds__(256)
gemm_bias_relu(const float* __restrict__ A, const float* __restrict__ B,
               const float* __restrict__ bias, float* __restrict__ C,
               int M, int N, int K) {
    __shared__ float As[BK][BM + 4];
    __shared__ float Bs[BK][BN + 4];
    const int t  = threadIdx.x;
    const int NT = BN / TN;
    const int tx = t % NT;
    const int ty = t / NT;
    const int m0 = blockIdx.y * BM;
    const int n0 = blockIdx.x * BN;

    float acc[TM][TN] = {};

    for (int k0 = 0; k0 < K; k0 += BK) {
        for (int i = t; i < BM * BK / 4; i += 256) {
            int r = i / (BK / 4);
            int c = (i % (BK / 4)) * 4;
            float4 v = *reinterpret_cast<const float4*>(&A[(m0 + r) * K + k0 + c]);
            As[c + 0][r] = v.x; As[c + 1][r] = v.y;
            As[c + 2][r] = v.z; As[c + 3][r] = v.w;
        }
        for (int i = t; i < BN * BK / 4; i += 256) {
            int r = i / (BK / 4);
            int c = (i % (BK / 4)) * 4;
            float4 v = *reinterpret_cast<const float4*>(&B[(n0 + r) * K + k0 + c]);
            Bs[c + 0][r] = v.x; Bs[c + 1][r] = v.y;
            Bs[c + 2][r] = v.z; Bs[c + 3][r] = v.w;
        }
        __syncthreads();
        #pragma unroll
        for (int kk = 0; kk < BK; kk++) {
            float a[TM], b[TN];
            #pragma unroll
            for (int i = 0; i < TM; i++) a[i] = As[kk][ty * TM + i];
            #pragma unroll
            for (int j = 0; j < TN; j++) b[j] = Bs[kk][tx * TN + j];
            #pragma unroll
            for (int i = 0; i < TM; i++)
                #pragma unroll
                for (int j = 0; j < TN; j++)
                    acc[i][j] = fmaf(a[i], b[j], acc[i][j]);
        }
        __syncthreads();
    }

    #pragma unroll
    for (int i = 0; i < TM; i++) {
        int row = m0 + ty * TM + i;
        #pragma unroll
        for (int j = 0; j < TN; j++) {
            int col = n0 + tx * TN + j;
            float v = acc[i][j] + bias[col];
            C[row * N + col] = fmaxf(v, 0.f);
        }
    }
}

// ---------------- y[M,64] = x[M,64] @ W[64,64].T + b (no activation) ----------------
__global__ void __launch_bounds__(256)
lin64_kernel(const float* __restrict__ x, const float* __restrict__ W,
             const float* __restrict__ b, float* __restrict__ y) {
    __shared__ float Ws[64][65];
    __shared__ float xs[16][64];
    int t = threadIdx.x;
    for (int i = t; i < 4096; i += 256) Ws[i >> 6][i & 63] = W[i];
    int r0 = blockIdx.x * 16;
    if (t < 256) ((float4*)xs)[t] = ((const float4*)(x + r0 * 64))[t];
    __syncthreads();
    int j = t & 63, g = t >> 6;
    float acc[4] = {};
    for (int c = 0; c < 64; c++) {
        float w = Ws[j][c];
        #pragma unroll
        for (int rr = 0; rr < 4; rr++)
            acc[rr] = fmaf(xs[rr * 4 + g][c], w, acc[rr]);
    }
    float bj = b[j];
    #pragma unroll
    for (int rr = 0; rr < 4; rr++)
        y[(r0 + rr * 4 + g) * 64 + j] = acc[rr] + bj;
}

// ---------------- fused broadcast-relu double reduction ----------------
// S_r[q,j] += sum_l relu(ra[q,j]+pa[l,j]);  S_p[l,j] += sum_q relu(...)
// tile: 64 q  x 128 l.  thread: j = t&63, group g = t>>6 owns 32 l's in registers.
__global__ void __launch_bounds__(256, 2)
relusum_kernel(const float* __restrict__ ra, const float* __restrict__ pa) {
    extern __shared__ float sm[];
    float* ra_s = sm;             // 64*64
    float* sr_s = sm + 64 * 64;   // 4*64*64 (per-group S_r partials)
    int t = threadIdx.x;
    int j = t & 63, g = t >> 6;
    int l0 = blockIdx.x * 128;
    int q0 = blockIdx.y * 64;
    int lb = l0 + g * 32;

    float pa_loc[32], sp_loc[32];
    #pragma unroll
    for (int li = 0; li < 32; li++) {
        pa_loc[li] = pa[(lb + li) * 64 + j];
        sp_loc[li] = 0.f;
    }
    for (int i = t; i < 1024; i += 256)
        ((float4*)ra_s)[i] = ((const float4*)(ra + q0 * 64))[i];
    __syncthreads();

    for (int q = 0; q < 64; q++) {
        float raq = ra_s[q * 64 + j];
        float s0 = 0.f, s1 = 0.f, s2 = 0.f, s3 = 0.f;
        #pragma unroll
        for (int li = 0; li < 32; li += 4) {
            float v0 = fmaxf(raq + pa_loc[li + 0], 0.f);
            float v1 = fmaxf(raq + pa_loc[li + 1], 0.f);
            float v2 = fmaxf(raq + pa_loc[li + 2], 0.f);
            float v3 = fmaxf(raq + pa_loc[li + 3], 0.f);
            sp_loc[li + 0] += v0; sp_loc[li + 1] += v1;
            sp_loc[li + 2] += v2; sp_loc[li + 3] += v3;
            s0 += v0; s1 += v1; s2 += v2; s3 += v3;
        }
        sr_s[(g * 64 + q) * 64 + j] = (s0 + s1) + (s2 + s3);
    }
    __syncthreads();

    #pragma unroll
    for (int li = 0; li < 32; li++)
        atomicAdd(&g_Sp[(lb + li) * 64 + j], sp_loc[li]);
    for (int idx = t; idx < 4096; idx += 256) {
        int q = idx >> 6, jj = idx & 63;
        float s = (sr_s[q * 64 + jj] + sr_s[(64 + q) * 64 + jj]) +
                  (sr_s[(128 + q) * 64 + jj] + sr_s[(192 + q) * 64 + jj]);
        atomicAdd(&g_Sr[(q0 + q) * 64 + jj], s);
    }
}

// ---------------- p_gate = sigmoid(Sp/Q @ Wa.T + ba); prot = max_l k*(1+p_gate) ----
__global__ void __launch_bounds__(256)
pgate_prot_kernel(const float* __restrict__ Wa, const float* __restrict__ ba) {
    __shared__ float Ws[64][65];
    __shared__ float sps[16][64];
    __shared__ float red[4][64];
    int t = threadIdx.x;
    for (int i = t; i < 4096; i += 256) Ws[i >> 6][i & 63] = Wa[i];
    int l0 = blockIdx.x * 16;
    if (t < 256) ((float4*)sps)[t] = ((const float4*)(g_Sp + l0 * 64))[t];
    __syncthreads();
    int j = t & 63, g = t >> 6;
    float acc[4] = {};
    for (int c = 0; c < 64; c++) {
        float w = Ws[j][c];
        #pragma unroll
        for (int rr = 0; rr < 4; rr++)
            acc[rr] = fmaf(sps[rr * 4 + g][c], w, acc[rr]);
    }
    float bj = ba[j];
    float mx = 0.f;
    #pragma unroll
    for (int rr = 0; rr < 4; rr++) {
        int l = l0 + rr * 4 + g;
        float gate = 1.f / (1.f + expf(-(acc[rr] * (1.f / 512.f) + bj)));
        float cand = g_k[l * 64 + j] * (1.f + gate);  // k>=0 -> cand>=0
        mx = fmaxf(mx, cand);
    }
    red[g][j] = mx;
    __syncthreads();
    if (t < 64) {
        float m = fmaxf(fmaxf(red[0][t], red[1][t]), fmaxf(red[2][t], red[3][t]));
        atomicMax(reinterpret_cast<unsigned*>(&g_prot[t]), __float_as_uint(m));
    }
}

// ---------------- r_gate, ctx, 3-layer MLP, output ----------------
__global__ void __launch_bounds__(256)
final_kernel(const float* __restrict__ Wa,  const float* __restrict__ ba,
             const float* __restrict__ Wf1, const float* __restrict__ bf1,
             const float* __restrict__ Wf2, const float* __restrict__ bf2,
             const float* __restrict__ Wf3, const float* __restrict__ bf3,
             float* __restrict__ out) {
    __shared__ float Ws[64][65];
    __shared__ float srs[8][64];
    __shared__ float rs[8][64];
    __shared__ float ctx[8][128];
    __shared__ float h1s[8][256];
    __shared__ float h2s[8][128];
    __shared__ float prot_s[64];
    int t = threadIdx.x;
    int q0 = blockIdx.x * 8;
    for (int i = t; i < 4096; i += 256) Ws[i >> 6][i & 63] = Wa[i];
    if (t < 128) {
        ((float4*)srs)[t] = ((const float4*)(g_Sr + q0 * 64))[t];
        ((float4*)rs)[t]  = ((const float4*)(g_r  + q0 * 64))[t];
    }
    if (t < 64) prot_s[t] = g_prot[t];
    __syncthreads();

    // stage A: r_gate + ctx
    {
        int j = t & 63, g = t >> 6;
        float a0 = 0.f, a1 = 0.f;
        for (int c = 0; c < 64; c++) {
            float w = Ws[j][c];
            a0 = fmaf(srs[g][c], w, a0);
            a1 = fmaf(srs[g + 4][c], w, a1);
        }
        float bj = ba[j];
        float g0 = 1.f / (1.f + expf(-(a0 * (1.f / 4096.f) + bj)));
        float g1 = 1.f / (1.f + expf(-(a1 * (1.f / 4096.f) + bj)));
        ctx[g][j]        = rs[g][j]     * (1.f + g0);
        ctx[g + 4][j]    = rs[g + 4][j] * (1.f + g1);
        ctx[g][64 + j]   = prot_s[j];
        ctx[g + 4][64 + j] = prot_s[j];
    }
    __syncthreads();

    // stage B: h1 = leaky_relu(ctx @ Wf1.T + bf1), j = t (0..255)
    {
        float acc[8] = {};
        const float* wrow = Wf1 + t * 128;
        for (int c = 0; c < 128; c++) {
            float w = wrow[c];
            #pragma unroll
            for (int qq = 0; qq < 8; qq++)
                acc[qq] = fmaf(ctx[qq][c], w, acc[qq]);
        }
        float bj = bf1[t];
        #pragma unroll
        for (int qq = 0; qq < 8; qq++) {
            float v = acc[qq] + bj;
            h1s[qq][t] = v >= 0.f ? v : 0.01f * v;
        }
    }
    __syncthreads();

    // stage C: h2 = leaky_relu(h1 @ Wf2.T + bf2)
    {
        int jj = t & 127, h = t >> 7;
        float acc[4] = {};
        const float* wrow = Wf2 + jj * 256;
        for (int c = 0; c < 256; c++) {
            float w = wrow[c];
            #pragma unroll
            for (int qq = 0; qq < 4; qq++)
                acc[qq] = fmaf(h1s[h * 4 + qq][c], w, acc[qq]);
        }
        float bj = bf2[jj];
        #pragma unroll
        for (int qq = 0; qq < 4; qq++) {
            float v = acc[qq] + bj;
            h2s[h * 4 + qq][jj] = v >= 0.f ? v : 0.01f * v;
        }
    }
    __syncthreads();

    // stage D: out[q] = h2 @ Wf3.T + bf3
    {
        int w = t >> 5, lane = t & 31;
        float s = 0.f;
        #pragma unroll
        for (int k4 = 0; k4 < 4; k4++)
            s = fmaf(h2s[w][lane + k4 * 32], Wf3[lane + k4 * 32], s);
        #pragma unroll
        for (int off = 16; off > 0; off >>= 1)
            s += __shfl_down_sync(0xffffffff, s, off);
        if (lane == 0) out[q0 + w] = s + bf3[0];
    }
}

// ---------------- launch ----------------
extern "C" void kernel_launch(void* const* d_in, const int* in_sizes, int n_in,
                              void* d_out, int out_size) {
    const float* reactions = (const float*)d_in[0];
    const float* protein   = (const float*)d_in[1];
    const float* Wc  = (const float*)d_in[2];
    const float* bc  = (const float*)d_in[3];
    const float* W1  = (const float*)d_in[4];
    const float* b1  = (const float*)d_in[5];
    const float* W2  = (const float*)d_in[6];
    const float* b2  = (const float*)d_in[7];
    const float* Wa  = (const float*)d_in[8];
    const float* ba  = (const float*)d_in[9];
    const float* Wpa = (const float*)d_in[10];
    const float* bpa = (const float*)d_in[11];
    const float* Wra = (const float*)d_in[12];
    const float* bra = (const float*)d_in[13];
    const float* Wf1 = (const float*)d_in[14];
    const float* bf1 = (const float*)d_in[15];
    const float* Wf2 = (const float*)d_in[16];
    const float* bf2 = (const float*)d_in[17];
    const float* Wf3 = (const float*)d_in[18];
    const float* bf3 = (const float*)d_in[19];
    float* out = (float*)d_out;

    float *pP, *pK, *pPa, *pR, *pRa;
    cudaGetSymbolAddress((void**)&pP,  g_p);
    cudaGetSymbolAddress((void**)&pK,  g_k);
    cudaGetSymbolAddress((void**)&pPa, g_pa);
    cudaGetSymbolAddress((void**)&pR,  g_r);
    cudaGetSymbolAddress((void**)&pRa, g_ra);

    zero_init_kernel<<<288, 256>>>();

    // p = relu(protein @ Wc.T + bc)   [4096,1024]x[256,1024] -> [4096,256]
    gemm_bias_relu<64, 64, 16, 4, 4><<<dim3(4, 64), 256>>>(protein, Wc, bc, pP, 4096, 256, 1024);
    // k = relu(p @ W1.T + b1)         [4096,256]x[64,256]    -> [4096,64]
    gemm_bias_relu<32, 64, 16, 2, 4><<<dim3(1, 128), 256>>>(pP, W1, b1, pK, 4096, 64, 256);
    // r = relu(reactions @ W2.T + b2) [512,256]x[64,256]     -> [512,64]
    gemm_bias_relu<32, 64, 16, 2, 4><<<dim3(1, 16), 256>>>(reactions, W2, b2, pR, 512, 64, 256);
    // pa = k @ Wpa.T + bpa; ra = r @ Wra.T + bra
    lin64_kernel<<<256, 256>>>(pK, Wpa, bpa, pPa);
    lin64_kernel<<<32, 256>>>(pR, Wra, bra, pRa);

    // S_r, S_p double reduction (mean commutes with trailing linear layer)
    const int smem = (64 * 64 + 4 * 64 * 64) * 4;  // 80 KB
    cudaFuncSetAttribute(relusum_kernel, cudaFuncAttributeMaxDynamicSharedMemorySize, smem);
    relusum_kernel<<<dim3(32, 8), 256, smem>>>(pRa, pPa);

    // p_gate -> prot (max over L)
    pgate_prot_kernel<<<256, 256>>>(Wa, ba);
    // r_gate -> ctx -> MLP -> out
    final_kernel<<<64, 256>>>(Wa, ba, Wf1, bf1, Wf2, bf2, Wf3, bf3, out);
}

// round 6
// speedup vs baseline: 1.2645x; 1.2645x over previous
#include <cuda_runtime.h>
#include <cuda_bf16.h>
#include <math.h>
#include <stdint.h>

// Problem sizes
#define QN 512
#define LN 4096

// ---------------- scratch (device globals; no allocation allowed) ----------------
__device__ float g_p [LN * 256];   // relu(protein @ Wc.T + bc)
__device__ float g_k [LN * 64];    // relu(p @ W1.T + b1)
__device__ float g_pa[LN * 64];    // k @ Wpa.T + bpa
__device__ float g_Sp[LN * 64];    // sum_q relu(ra+pa)
__device__ float g_r [QN * 64];    // relu(reactions @ W2.T + b2)
__device__ float g_ra[QN * 64];    // r @ Wra.T + bra
__device__ float g_Sr[QN * 64];    // sum_l relu(ra+pa)
__device__ float g_prot[64];       // max_l (k * (1+p_gate))

// ---------------- init: zero the atomic accumulators ----------------
__global__ void zero_init_kernel() {
    int i = blockIdx.x * blockDim.x + threadIdx.x;
    int stride = gridDim.x * blockDim.x;
    for (int x = i; x < LN * 64; x += stride) g_Sp[x] = 0.f;
    for (int x = i; x < QN * 64; x += stride) g_Sr[x] = 0.f;
    if (i < 64) g_prot[i] = 0.f;
}

// =================== mma.sync bf16 GEMM with in-kernel hi/lo split ===================
// C[M,N] = relu(A[M,K] @ B[N,K].T + bias), fp32 in/out.
// Internally: a ~= a_hi + a_lo (bf16 each); C = hi*hi + hi*lo + lo*hi (drop lo*lo).
// CTA tile 128x64 (M x N), 8 warps in 4x2, warp tile 32x32 (2x4 m16n8k16 tiles).
// BK = 32 (2 k-steps of 16). Double-buffered smem, register-staged LDG prefetch.

__device__ __forceinline__ void mma16816(float* c, const uint32_t* a, const uint32_t* b) {
    asm volatile(
        "mma.sync.aligned.m16n8k16.row.col.f32.bf16.bf16.f32 "
        "{%0,%1,%2,%3}, {%4,%5,%6,%7}, {%8,%9}, {%0,%1,%2,%3};\n"
        : "+f"(c[0]), "+f"(c[1]), "+f"(c[2]), "+f"(c[3])
        : "r"(a[0]), "r"(a[1]), "r"(a[2]), "r"(a[3]), "r"(b[0]), "r"(b[1]));
}

// split 8 fp32 -> 8 bf16 hi (uint4) + 8 bf16 lo (uint4)
__device__ __forceinline__ void split_pack8(const float* f, uint4& hi, uint4& lo) {
    uint32_t h[4], l[4];
    #pragma unroll
    for (int e = 0; e < 4; e++) {
        __nv_bfloat16 h0 = __float2bfloat16_rn(f[2 * e]);
        __nv_bfloat16 h1 = __float2bfloat16_rn(f[2 * e + 1]);
        __nv_bfloat16 l0 = __float2bfloat16_rn(f[2 * e]     - __bfloat162float(h0));
        __nv_bfloat16 l1 = __float2bfloat16_rn(f[2 * e + 1] - __bfloat162float(h1));
        h[e] = (uint32_t)__bfloat16_as_ushort(h0) | ((uint32_t)__bfloat16_as_ushort(h1) << 16);
        l[e] = (uint32_t)__bfloat16_as_ushort(l0) | ((uint32_t)__bfloat16_as_ushort(l1) << 16);
    }
    hi = make_uint4(h[0], h[1], h[2], h[3]);
    lo = make_uint4(l[0], l[1], l[2], l[3]);
}

// smem layout (elements of bf16), row stride 40 (=80B => bank stride 20: the
// fragment LDS pattern bank = (20*r + c) mod 32 is conflict-free for r<8,c<4)
#define SR 40
#define ST_AL (128 * SR)              // 5120
#define ST_BH (2 * 128 * SR)          // 10240
#define ST_BL (2 * 128 * SR + 64 * SR)// 12800
#define STAGE (2 * 128 * SR + 2 * 64 * SR)  // 15360 elems = 30720 B
#define GEMM_SMEM_BYTES (2 * STAGE * 2)     // 61440 B

__global__ void __launch_bounds__(256)
gemm_mma_split(const float* __restrict__ A, const float* __restrict__ B,
               const float* __restrict__ bias, int K, int ldc,
               float* __restrict__ C) {
    extern __shared__ __nv_bfloat16 sm[];
    const int t    = threadIdx.x;
    const int lane = t & 31;
    const int wid  = t >> 5;
    const int wm   = wid >> 1;        // 0..3
    const int wn   = wid & 1;         // 0..1
    const int m0   = blockIdx.y * 128;
    const int n0   = blockIdx.x * 64;
    const int r    = lane >> 2;       // 0..7
    const int cq   = (lane & 3) * 2;  // 0,2,4,6

    float acc[2][4][4] = {};

    // staging: A two units (rows ar0 and ar0+64, 8 floats each), B one unit
    const int ar0 = t >> 2;           // 0..63
    const int au  = (t & 3) * 8;      // 0,8,16,24
    float fa0[8], fa1[8], fb[8];

    const int nch = K >> 5;

    // ---- LDG chunk k0 into registers ----
    #define LDG_CHUNK(k0) do {                                                  \
        const float* _s0 = A + (size_t)(m0 + ar0) * K + (k0) + au;              \
        *(float4*)&fa0[0] = *(const float4*)_s0;                                \
        *(float4*)&fa0[4] = *(const float4*)(_s0 + 4);                          \
        const float* _s1 = A + (size_t)(m0 + ar0 + 64) * K + (k0) + au;         \
        *(float4*)&fa1[0] = *(const float4*)_s1;                                \
        *(float4*)&fa1[4] = *(const float4*)(_s1 + 4);                          \
        const float* _s2 = B + (size_t)(n0 + ar0) * K + (k0) + au;              \
        *(float4*)&fb[0]  = *(const float4*)_s2;                                \
        *(float4*)&fb[4]  = *(const float4*)(_s2 + 4);                          \
    } while (0)

    LDG_CHUNK(0);

    for (int c = 0; c < nch; c++) {
        const int st = c & 1;
        // ---- convert + STS into buffer st ----
        {
            __nv_bfloat16* base = sm + st * STAGE;
            uint4 hi, lo;
            split_pack8(fa0, hi, lo);
            *(uint4*)(base + ar0 * SR + au)                 = hi;
            *(uint4*)(base + ST_AL + ar0 * SR + au)         = lo;
            split_pack8(fa1, hi, lo);
            *(uint4*)(base + (ar0 + 64) * SR + au)          = hi;
            *(uint4*)(base + ST_AL + (ar0 + 64) * SR + au)  = lo;
            split_pack8(fb, hi, lo);
            *(uint4*)(base + ST_BH + ar0 * SR + au)         = hi;
            *(uint4*)(base + ST_BL + ar0 * SR + au)         = lo;
        }
        __syncthreads();
        if (c + 1 < nch) LDG_CHUNK((c + 1) << 5);  // prefetch overlaps mma below

        // ---- compute on buffer st ----
        {
            const __nv_bfloat16* Ah = sm + st * STAGE;
            const __nv_bfloat16* Al = Ah + ST_AL;
            const __nv_bfloat16* Bh = Ah + ST_BH;
            const __nv_bfloat16* Bl = Ah + ST_BL;
            #pragma unroll
            for (int ks = 0; ks < 2; ks++) {
                const int ka = ks * 16 + cq;
                uint32_t ah[2][4], al[2][4], bh[4][2], bl[4][2];
                #pragma unroll
                for (int ti = 0; ti < 2; ti++) {
                    int row = wm * 32 + ti * 16 + r;
                    ah[ti][0] = *(const uint32_t*)(Ah + row * SR + ka);
                    ah[ti][1] = *(const uint32_t*)(Ah + (row + 8) * SR + ka);
                    ah[ti][2] = *(const uint32_t*)(Ah + row * SR + ka + 8);
                    ah[ti][3] = *(const uint32_t*)(Ah + (row + 8) * SR + ka + 8);
                    al[ti][0] = *(const uint32_t*)(Al + row * SR + ka);
                    al[ti][1] = *(const uint32_t*)(Al + (row + 8) * SR + ka);
                    al[ti][2] = *(const uint32_t*)(Al + row * SR + ka + 8);
                    al[ti][3] = *(const uint32_t*)(Al + (row + 8) * SR + ka + 8);
                }
                #pragma unroll
                for (int tj = 0; tj < 4; tj++) {
                    int col = wn * 32 + tj * 8 + r;
                    bh[tj][0] = *(const uint32_t*)(Bh + col * SR + ka);
                    bh[tj][1] = *(const uint32_t*)(Bh + col * SR + ka + 8);
                    bl[tj][0] = *(const uint32_t*)(Bl + col * SR + ka);
                    bl[tj][1] = *(const uint32_t*)(Bl + col * SR + ka + 8);
                }
                #pragma unroll
                for (int ti = 0; ti < 2; ti++)
                    #pragma unroll
                    for (int tj = 0; tj < 4; tj++) {
                        mma16816(acc[ti][tj], ah[ti], bh[tj]);
                        mma16816(acc[ti][tj], ah[ti], bl[tj]);
                        mma16816(acc[ti][tj], al[ti], bh[tj]);
                    }
            }
        }
        __syncthreads();
    }
    #undef LDG_CHUNK

    // ---- epilogue: bias + relu + store fp32 ----
    #pragma unroll
    for (int ti = 0; ti < 2; ti++) {
        int row = m0 + wm * 32 + ti * 16 + r;
        #pragma unroll
        for (int tj = 0; tj < 4; tj++) {
            int col = n0 + wn * 32 + tj * 8 + cq;
            float b0 = __ldg(bias + col), b1 = __ldg(bias + col + 1);
            float2 v0, v1;
            v0.x = fmaxf(acc[ti][tj][0] + b0, 0.f);
            v0.y = fmaxf(acc[ti][tj][1] + b1, 0.f);
            v1.x = fmaxf(acc[ti][tj][2] + b0, 0.f);
            v1.y = fmaxf(acc[ti][tj][3] + b1, 0.f);
            *(float2*)&C[(size_t)row * ldc + col]       = v0;
            *(float2*)&C[(size_t)(row + 8) * ldc + col] = v1;
        }
    }
}

// ---------------- tiled SGEMM (small): C = relu(A[M,K] @ B[N,K].T + bias) ----------
template <int BM, int BN, int BK, int TM, int TN>
__global__ void __launch_bounds__(256)
gemm_bias_relu(const float* __restrict__ A, const float* __restrict__ B,
               const float* __restrict__ bias, float* __restrict__ C,
               int M, int N, int K) {
    __shared__ float As[BK][BM + 4];
    __shared__ float Bs[BK][BN + 4];
    const int t  = threadIdx.x;
    const int NT = BN / TN;
    const int tx = t % NT;
    const int ty = t / NT;
    const int m0 = blockIdx.y * BM;
    const int n0 = blockIdx.x * BN;
    float acc[TM][TN] = {};
    for (int k0 = 0; k0 < K; k0 += BK) {
        for (int i = t; i < BM * BK / 4; i += 256) {
            int r = i / (BK / 4);
            int c = (i % (BK / 4)) * 4;
            float4 v = *reinterpret_cast<const float4*>(&A[(m0 + r) * K + k0 + c]);
            As[c + 0][r] = v.x; As[c + 1][r] = v.y;
            As[c + 2][r] = v.z; As[c + 3][r] = v.w;
        }
        for (int i = t; i < BN * BK / 4; i += 256) {
            int r = i / (BK / 4);
            int c = (i % (BK / 4)) * 4;
            float4 v = *reinterpret_cast<const float4*>(&B[(n0 + r) * K + k0 + c]);
            Bs[c + 0][r] = v.x; Bs[c + 1][r] = v.y;
            Bs[c + 2][r] = v.z; Bs[c + 3][r] = v.w;
        }
        __syncthreads();
        #pragma unroll
        for (int kk = 0; kk < BK; kk++) {
            float a[TM], b[TN];
            #pragma unroll
            for (int i = 0; i < TM; i++) a[i] = As[kk][ty * TM + i];
            #pragma unroll
            for (int j = 0; j < TN; j++) b[j] = Bs[kk][tx * TN + j];
            #pragma unroll
            for (int i = 0; i < TM; i++)
                #pragma unroll
                for (int j = 0; j < TN; j++)
                    acc[i][j] = fmaf(a[i], b[j], acc[i][j]);
        }
        __syncthreads();
    }
    #pragma unroll
    for (int i = 0; i < TM; i++) {
        int row = m0 + ty * TM + i;
        #pragma unroll
        for (int j = 0; j < TN; j++) {
            int col = n0 + tx * TN + j;
            float v = acc[i][j] + bias[col];
            C[row * N + col] = fmaxf(v, 0.f);
        }
    }
}

// ---------------- y[M,64] = x[M,64] @ W[64,64].T + b ----------------
__global__ void __launch_bounds__(256)
lin64_kernel(const float* __restrict__ x, const float* __restrict__ W,
             const float* __restrict__ b, float* __restrict__ y) {
    __shared__ float Ws[64][65];
    __shared__ float xs[16][64];
    int t = threadIdx.x;
    for (int i = t; i < 4096; i += 256) Ws[i >> 6][i & 63] = W[i];
    int r0 = blockIdx.x * 16;
    if (t < 256) ((float4*)xs)[t] = ((const float4*)(x + r0 * 64))[t];
    __syncthreads();
    int j = t & 63, g = t >> 6;
    float acc[4] = {};
    for (int c = 0; c < 64; c++) {
        float w = Ws[j][c];
        #pragma unroll
        for (int rr = 0; rr < 4; rr++)
            acc[rr] = fmaf(xs[rr * 4 + g][c], w, acc[rr]);
    }
    float bj = b[j];
    #pragma unroll
    for (int rr = 0; rr < 4; rr++)
        y[(r0 + rr * 4 + g) * 64 + j] = acc[rr] + bj;
}

// ---------------- fused broadcast-relu double reduction ----------------
__global__ void __launch_bounds__(256, 2)
relusum_kernel(const float* __restrict__ ra, const float* __restrict__ pa) {
    extern __shared__ float smf[];
    float* ra_s = smf;             // 64*64
    float* sr_s = smf + 64 * 64;   // 4*64*64
    int t = threadIdx.x;
    int j = t & 63, g = t >> 6;
    int l0 = blockIdx.x * 128;
    int q0 = blockIdx.y * 64;
    int lb = l0 + g * 32;

    float pa_loc[32], sp_loc[32];
    #pragma unroll
    for (int li = 0; li < 32; li++) {
        pa_loc[li] = pa[(lb + li) * 64 + j];
        sp_loc[li] = 0.f;
    }
    for (int i = t; i < 1024; i += 256)
        ((float4*)ra_s)[i] = ((const float4*)(ra + q0 * 64))[i];
    __syncthreads();

    for (int q = 0; q < 64; q++) {
        float raq = ra_s[q * 64 + j];
        float s0 = 0.f, s1 = 0.f, s2 = 0.f, s3 = 0.f;
        #pragma unroll
        for (int li = 0; li < 32; li += 4) {
            float v0 = fmaxf(raq + pa_loc[li + 0], 0.f);
            float v1 = fmaxf(raq + pa_loc[li + 1], 0.f);
            float v2 = fmaxf(raq + pa_loc[li + 2], 0.f);
            float v3 = fmaxf(raq + pa_loc[li + 3], 0.f);
            sp_loc[li + 0] += v0; sp_loc[li + 1] += v1;
            sp_loc[li + 2] += v2; sp_loc[li + 3] += v3;
            s0 += v0; s1 += v1; s2 += v2; s3 += v3;
        }
        sr_s[(g * 64 + q) * 64 + j] = (s0 + s1) + (s2 + s3);
    }
    __syncthreads();

    #pragma unroll
    for (int li = 0; li < 32; li++)
        atomicAdd(&g_Sp[(lb + li) * 64 + j], sp_loc[li]);
    for (int idx = t; idx < 4096; idx += 256) {
        int q = idx >> 6, jj = idx & 63;
        float s = (sr_s[q * 64 + jj] + sr_s[(64 + q) * 64 + jj]) +
                  (sr_s[(128 + q) * 64 + jj] + sr_s[(192 + q) * 64 + jj]);
        atomicAdd(&g_Sr[(q0 + q) * 64 + jj], s);
    }
}

// ---------------- p_gate / prot ----------------
__global__ void __launch_bounds__(256)
pgate_prot_kernel(const float* __restrict__ Wa, const float* __restrict__ ba) {
    __shared__ float Ws[64][65];
    __shared__ float sps[16][64];
    __shared__ float red[4][64];
    int t = threadIdx.x;
    for (int i = t; i < 4096; i += 256) Ws[i >> 6][i & 63] = Wa[i];
    int l0 = blockIdx.x * 16;
    if (t < 256) ((float4*)sps)[t] = ((const float4*)(g_Sp + l0 * 64))[t];
    __syncthreads();
    int j = t & 63, g = t >> 6;
    float acc[4] = {};
    for (int c = 0; c < 64; c++) {
        float w = Ws[j][c];
        #pragma unroll
        for (int rr = 0; rr < 4; rr++)
            acc[rr] = fmaf(sps[rr * 4 + g][c], w, acc[rr]);
    }
    float bj = ba[j];
    float mx = 0.f;
    #pragma unroll
    for (int rr = 0; rr < 4; rr++) {
        int l = l0 + rr * 4 + g;
        float gate = 1.f / (1.f + expf(-(acc[rr] * (1.f / 512.f) + bj)));
        float cand = g_k[l * 64 + j] * (1.f + gate);
        mx = fmaxf(mx, cand);
    }
    red[g][j] = mx;
    __syncthreads();
    if (t < 64) {
        float m = fmaxf(fmaxf(red[0][t], red[1][t]), fmaxf(red[2][t], red[3][t]));
        atomicMax(reinterpret_cast<unsigned*>(&g_prot[t]), __float_as_uint(m));
    }
}

// ---------------- r_gate, ctx, 3-layer MLP, output ----------------
__global__ void __launch_bounds__(256)
final_kernel(const float* __restrict__ Wa,  const float* __restrict__ ba,
             const float* __restrict__ Wf1, const float* __restrict__ bf1,
             const float* __restrict__ Wf2, const float* __restrict__ bf2,
             const float* __restrict__ Wf3, const float* __restrict__ bf3,
             float* __restrict__ out) {
    __shared__ float Ws[64][65];
    __shared__ float srs[8][64];
    __shared__ float rs[8][64];
    __shared__ float ctx[8][128];
    __shared__ float h1s[8][256];
    __shared__ float h2s[8][128];
    __shared__ float prot_s[64];
    int t = threadIdx.x;
    int q0 = blockIdx.x * 8;
    for (int i = t; i < 4096; i += 256) Ws[i >> 6][i & 63] = Wa[i];
    if (t < 128) {
        ((float4*)srs)[t] = ((const float4*)(g_Sr + q0 * 64))[t];
        ((float4*)rs)[t]  = ((const float4*)(g_r  + q0 * 64))[t];
    }
    if (t < 64) prot_s[t] = g_prot[t];
    __syncthreads();
    {
        int j = t & 63, g = t >> 6;
        float a0 = 0.f, a1 = 0.f;
        for (int c = 0; c < 64; c++) {
            float w = Ws[j][c];
            a0 = fmaf(srs[g][c], w, a0);
            a1 = fmaf(srs[g + 4][c], w, a1);
        }
        float bj = ba[j];
        float g0 = 1.f / (1.f + expf(-(a0 * (1.f / 4096.f) + bj)));
        float g1 = 1.f / (1.f + expf(-(a1 * (1.f / 4096.f) + bj)));
        ctx[g][j]          = rs[g][j]     * (1.f + g0);
        ctx[g + 4][j]      = rs[g + 4][j] * (1.f + g1);
        ctx[g][64 + j]     = prot_s[j];
        ctx[g + 4][64 + j] = prot_s[j];
    }
    __syncthreads();
    {
        float acc[8] = {};
        const float* wrow = Wf1 + t * 128;
        for (int c = 0; c < 128; c++) {
            float w = wrow[c];
            #pragma unroll
            for (int qq = 0; qq < 8; qq++)
                acc[qq] = fmaf(ctx[qq][c], w, acc[qq]);
        }
        float bj = bf1[t];
        #pragma unroll
        for (int qq = 0; qq < 8; qq++) {
            float v = acc[qq] + bj;
            h1s[qq][t] = v >= 0.f ? v : 0.01f * v;
        }
    }
    __syncthreads();
    {
        int jj = t & 127, h = t >> 7;
        float acc[4] = {};
        const float* wrow = Wf2 + jj * 256;
        for (int c = 0; c < 256; c++) {
            float w = wrow[c];
            #pragma unroll
            for (int qq = 0; qq < 4; qq++)
                acc[qq] = fmaf(h1s[h * 4 + qq][c], w, acc[qq]);
        }
        float bj = bf2[jj];
        #pragma unroll
        for (int qq = 0; qq < 4; qq++) {
            float v = acc[qq] + bj;
            h2s[h * 4 + qq][jj] = v >= 0.f ? v : 0.01f * v;
        }
    }
    __syncthreads();
    {
        int w = t >> 5, lane = t & 31;
        float s = 0.f;
        #pragma unroll
        for (int k4 = 0; k4 < 4; k4++)
            s = fmaf(h2s[w][lane + k4 * 32], Wf3[lane + k4 * 32], s);
        #pragma unroll
        for (int off = 16; off > 0; off >>= 1)
            s += __shfl_down_sync(0xffffffff, s, off);
        if (lane == 0) out[q0 + w] = s + bf3[0];
    }
}

// ---------------- launch ----------------
extern "C" void kernel_launch(void* const* d_in, const int* in_sizes, int n_in,
                              void* d_out, int out_size) {
    const float* reactions = (const float*)d_in[0];
    const float* protein   = (const float*)d_in[1];
    const float* Wc  = (const float*)d_in[2];
    const float* bc  = (const float*)d_in[3];
    const float* W1  = (const float*)d_in[4];
    const float* b1  = (const float*)d_in[5];
    const float* W2  = (const float*)d_in[6];
    const float* b2  = (const float*)d_in[7];
    const float* Wa  = (const float*)d_in[8];
    const float* ba  = (const float*)d_in[9];
    const float* Wpa = (const float*)d_in[10];
    const float* bpa = (const float*)d_in[11];
    const float* Wra = (const float*)d_in[12];
    const float* bra = (const float*)d_in[13];
    const float* Wf1 = (const float*)d_in[14];
    const float* bf1 = (const float*)d_in[15];
    const float* Wf2 = (const float*)d_in[16];
    const float* bf2 = (const float*)d_in[17];
    const float* Wf3 = (const float*)d_in[18];
    const float* bf3 = (const float*)d_in[19];
    float* out = (float*)d_out;

    float *pP, *pK, *pPa, *pR, *pRa;
    cudaGetSymbolAddress((void**)&pP,  g_p);
    cudaGetSymbolAddress((void**)&pK,  g_k);
    cudaGetSymbolAddress((void**)&pPa, g_pa);
    cudaGetSymbolAddress((void**)&pR,  g_r);
    cudaGetSymbolAddress((void**)&pRa, g_ra);

    static bool attr_done = false;
    if (!attr_done) {
        cudaFuncSetAttribute(gemm_mma_split,
                             cudaFuncAttributeMaxDynamicSharedMemorySize, GEMM_SMEM_BYTES);
        cudaFuncSetAttribute(relusum_kernel,
                             cudaFuncAttributeMaxDynamicSharedMemorySize,
                             (64 * 64 + 4 * 64 * 64) * 4);
        attr_done = true;
    }

    zero_init_kernel<<<288, 256>>>();

    // p = relu(protein @ Wc.T + bc): [4096,1024] x [256,1024] -> [4096,256]  (HMMA split)
    gemm_mma_split<<<dim3(4, 32), 256, GEMM_SMEM_BYTES>>>(protein, Wc, bc, 1024, 256, pP);
    // k = relu(p @ W1.T + b1): [4096,256] x [64,256] -> [4096,64]            (HMMA split)
    gemm_mma_split<<<dim3(1, 32), 256, GEMM_SMEM_BYTES>>>(pP, W1, b1, 256, 64, pK);
    // pa = k @ Wpa.T + bpa
    lin64_kernel<<<256, 256>>>(pK, Wpa, bpa, pPa);
    // r = relu(reactions @ W2.T + b2)  (grid 64 to fix the latency-bound launch)
    gemm_bias_relu<8, 64, 16, 1, 2><<<dim3(1, 64), 256>>>(reactions, W2, b2, pR, 512, 64, 256);
    // ra = r @ Wra.T + bra
    lin64_kernel<<<32, 256>>>(pR, Wra, bra, pRa);

    // S_r, S_p double reduction (mean commutes with trailing linear layer)
    const int rsmem = (64 * 64 + 4 * 64 * 64) * 4;
    relusum_kernel<<<dim3(32, 8), 256, rsmem>>>(pRa, pPa);

    pgate_prot_kernel<<<256, 256>>>(Wa, ba);
    final_kernel<<<64, 256>>>(Wa, ba, Wf1, bf1, Wf2, bf2, Wf3, bf3, out);
}